// round 16
// baseline (speedup 1.0000x reference)
#include <cuda_runtime.h>
#include <stdint.h>
#include <stddef.h>

// ===========================================================================
// FARGAN vocoder. B=64, T=100, NSUB=4, S=64, HOP=256, IC=512.
// Stage 0: precompute ALL noise (partitionable threefry) -> g_nz
// Stage 1: input MLP for all frames (no recurrence)      -> g_X
// Stage 2: pack/transpose recurrent weights              -> g_wp
// Stage 3: sequential recurrent kernel, 64 CTAs x 384 thr, ONE row per CTA.
//          R10 plain-dot structure (proven best) + CTA start-time stagger to
//          de-synchronize the 64 CTAs' identical L2 weight bursts + noise
//          staging folded into the out phase.
// ===========================================================================

__device__ float g_A1[6400 * 512];
__device__ float g_H [6400 * 512];
__device__ float g_X [6400 * 256];
__device__ float4 g_wp[50176];       // packed transposed recurrent weights
__device__ uint2 g_kk[4000];
__device__ float g_nz[18022400];     // 400 steps * 45056 noise values

// packed-weight offsets in g_wp (float4 units)
#define OFF_FW     0
#define OFF_FWGLU  2048
#define OFF_WIH1   3072
#define OFF_WHH1   9216
#define OFF_GLU1   12288
#define OFF_WIH2   13312
#define OFF_WHH2   19456
#define OFF_GLU2   22528
#define OFF_WIH3   23552
#define OFF_WHH3   29696
#define OFF_GLU3   32768
#define OFF_SKIPD  33792
#define OFF_SKIPG  44032
#define OFF_OUT    48128

// ----------------------------- threefry2x32 --------------------------------
__device__ __forceinline__ uint32_t rotl32(uint32_t v, int s) {
    return (v << s) | (v >> (32 - s));
}
__device__ __forceinline__ uint2 tf2x32(uint2 key, uint2 ctr) {
    uint32_t ks0 = key.x, ks1 = key.y;
    uint32_t ks2 = ks0 ^ ks1 ^ 0x1BD11BDAu;
    uint32_t x0 = ctr.x + ks0, x1 = ctr.y + ks1;
#define TFR(r) { x0 += x1; x1 = rotl32(x1, (r)); x1 ^= x0; }
    TFR(13) TFR(15) TFR(26) TFR(6)   x0 += ks1; x1 += ks2 + 1u;
    TFR(17) TFR(29) TFR(16) TFR(24)  x0 += ks2; x1 += ks0 + 2u;
    TFR(13) TFR(15) TFR(26) TFR(6)   x0 += ks0; x1 += ks1 + 3u;
    TFR(17) TFR(29) TFR(16) TFR(24)  x0 += ks1; x1 += ks2 + 4u;
    TFR(13) TFR(15) TFR(26) TFR(6)   x0 += ks2; x1 += ks0 + 5u;
#undef TFR
    return make_uint2(x0, x1);
}
__device__ __forceinline__ float nzf(uint32_t r) {
    float u = __uint_as_float((r >> 9) | 0x3f800000u) - 1.0f;
    return (u - 0.5f) * (1.0f / 127.0f);
}
__device__ __forceinline__ float clip1(float v) { return fminf(fmaxf(v, -1.0f), 1.0f); }
__device__ __forceinline__ float sigm(float x) { return 1.0f / (1.0f + expf(-x)); }

// ------------------------- noise precomputation ----------------------------
__global__ void gen_keys() {
    int idx = blockIdx.x * 128 + threadIdx.x;
    if (idx >= 4000) return;
    int step = idx / 10, q = idx % 10;
    uint2 fkey = tf2x32(make_uint2(0u, 1u), make_uint2(0u, (uint32_t)step));
    g_kk[idx] = tf2x32(fkey, make_uint2(0u, (uint32_t)q));
}
__global__ void gen_noise() {
    int rem = blockIdx.x * 256 + threadIdx.x;   // [0, 45056)
    int step = blockIdx.y;
    int q, f;
    if (rem < 36864) { q = rem >> 12; f = rem & 4095; }
    else             { q = 9;         f = rem - 36864; }
    uint2 kk = g_kk[step * 10 + q];
    uint2 c = tf2x32(kk, make_uint2(0u, (uint32_t)f));
    g_nz[(size_t)step * 45056 + rem] = nzf(c.x ^ c.y);
}

// ----------------------------- input MLP -----------------------------------
__global__ void build_a1(const float* __restrict__ feats, const float* __restrict__ gf) {
    int idx = blockIdx.x * blockDim.x + threadIdx.x;
    if (idx >= 6400 * 512) return;
    int row = idx >> 9;
    int k = idx & 511;
    int t = row >> 6, b = row & 63;
    float v;
    if (k < 256) v = feats[(b * 256 + k) * 100 + t];
    else         v = gf[b * 256 + (k - 256)];
    g_A1[idx] = v;
}

template <int ACT>
__device__ __forceinline__ void gemm_body(const float* __restrict__ A,
                                          const float* __restrict__ W,
                                          const float* __restrict__ bias,
                                          float* __restrict__ out, int N, int K) {
    __shared__ float As[64][17];
    __shared__ float Bs[16][65];
    const int bm = blockIdx.x * 64, bn = blockIdx.y * 64;
    const int tx = threadIdx.x & 15, ty = threadIdx.x >> 4;
    float acc[4][4] = {};
    for (int k0 = 0; k0 < K; k0 += 16) {
#pragma unroll
        for (int i = 0; i < 4; i++) {
            int lin = threadIdx.x + i * 256;
            int r = lin >> 4, c = lin & 15;
            As[r][c] = A[(bm + r) * K + k0 + c];
            Bs[c][r] = W[(bn + r) * K + k0 + c];
        }
        __syncthreads();
#pragma unroll
        for (int kk = 0; kk < 16; kk++) {
            float a[4], bb[4];
#pragma unroll
            for (int i = 0; i < 4; i++) a[i] = As[ty * 4 + i][kk];
#pragma unroll
            for (int j = 0; j < 4; j++) bb[j] = Bs[kk][tx * 4 + j];
#pragma unroll
            for (int i = 0; i < 4; i++)
#pragma unroll
                for (int j = 0; j < 4; j++)
                    acc[i][j] = fmaf(a[i], bb[j], acc[i][j]);
        }
        __syncthreads();
    }
#pragma unroll
    for (int i = 0; i < 4; i++) {
        int m = bm + ty * 4 + i;
#pragma unroll
        for (int j = 0; j < 4; j++) {
            int nn = bn + tx * 4 + j;
            float v = acc[i][j] + bias[nn];
            if (ACT) v = tanhf(v);
            out[m * N + nn] = v;
        }
    }
}
__global__ __launch_bounds__(256) void gemm1(const float* __restrict__ W,
                                             const float* __restrict__ b) {
    gemm_body<1>(g_A1, W, b, g_H, 512, 512);
}
__global__ __launch_bounds__(256) void gemm2(const float* __restrict__ W,
                                             const float* __restrict__ b) {
    gemm_body<0>(g_H, W, b, g_X, 256, 512);
}

// ----------------------- weight transpose/pack -----------------------------
__global__ void packw(const float* __restrict__ src, int off, int N, int K4) {
    int idx = blockIdx.x * blockDim.x + threadIdx.x;
    if (idx >= N * K4) return;
    int n = idx % N, kq = idx / N;
    const float* s = src + n * (K4 * 4) + 4 * kq;
    g_wp[off + idx] = make_float4(s[0], s[1], s[2], s[3]);
}

// ----------------------------- single-row dot ------------------------------
template <int LEN>
__device__ __forceinline__ float dotp1(const float4* __restrict__ wp, int n, int N,
                                       const float* __restrict__ x) {
    const float4* xa = reinterpret_cast<const float4*>(x);
    float a0 = 0.f, a1 = 0.f;
#pragma unroll
    for (int i = 0; i < LEN; i++) {
        float4 w = wp[i * N + n];
        float4 p = xa[i];
        a0 = fmaf(w.x, p.x, a0); a1 = fmaf(w.y, p.y, a1);
        a0 = fmaf(w.z, p.z, a0); a1 = fmaf(w.w, p.w, a1);
    }
    return a0 + a1;
}

// --------------------------- recurrent kernel ------------------------------
__global__ __launch_bounds__(384, 1) void fargan_rnn(float* __restrict__ out) {
    const int tid = threadIdx.x;
    const int b = blockIdx.x;             // ONE batch row per CTA

    __shared__ __align__(16) float sfr[320];    // [g1|g2|g3|fw|prevn]
    __shared__ __align__(16) float fwin[128];   // [sub_noised | s3]
    __shared__ __align__(16) float tmp[64];
    __shared__ __align__(16) float h1[64], h2[64], h3[64];
    __shared__ __align__(16) float prev[64];
    __shared__ __align__(16) float skb[128], sk2[128];
    __shared__ __align__(16) float part_a[384], part_b[384];
    __shared__ __align__(16) float nbuf[704];   // streams 0-8 @ q*64, 9 @ 576

#define STAGE_NOISE(STEP, BASE, STRIDE)                                        \
    {                                                                          \
        const float* nsrc = g_nz + (size_t)(STEP) * 45056;                     \
        for (int c = (BASE); c < 176; c += (STRIDE)) {                         \
            int goff, soff;                                                    \
            if (c < 144) {                      /* streams 0..8 */             \
                int q = c >> 4, l = c & 15;                                    \
                goff = q * 4096 + b * 64 + l * 4;                              \
                soff = q * 64 + l * 4;                                         \
            } else {                            /* stream 9 */                 \
                int l = c - 144;                                               \
                goff = 36864 + b * 128 + l * 4;                                \
                soff = 576 + l * 4;                                            \
            }                                                                  \
            *reinterpret_cast<float4*>(nbuf + soff) =                          \
                *reinterpret_cast<const float4*>(nsrc + goff);                 \
        }                                                                      \
    }

    if (tid < 64) {
        h1[tid] = h2[tid] = h3[tid] = 0.f;
        prev[tid] = 0.f;
    }
    if (tid < 128) fwin[tid] = 0.f;
    STAGE_NOISE(0, tid, 384);
    __syncthreads();

    // ---- CTA start stagger: spread the 64 identical CTAs over ~1 step so
    //      their per-phase L2 weight bursts stop colliding at the LTS cap.
    //      Timing-only; output is unaffected; graph-capture safe. ----
    {
        unsigned long long delay = (unsigned long long)((b & 7) * 2048);
        unsigned long long start = clock64();
        while (clock64() - start < delay) { }
    }
    __syncthreads();

#pragma unroll 1
    for (int t = 0; t < 100; t++) {
#pragma unroll 1
        for (int s = 0; s < 4; s++) {
            const int step = t * 4 + s;

            // ---- phase A: noise sub + prev, shift s3 (64 threads) ----
            if (tid < 64) {
                int j = tid;
                float sx = g_X[(t * 64 + b) * 256 + s * 64 + j];
                float olds = fwin[j];
                fwin[64 + j] = olds;                          // s3
                fwin[j] = clip1(sx + nbuf[j]);                // stream 0
                sfr[256 + j] = clip1(prev[j] + nbuf[64 + j]); // stream 1
            }
            __syncthreads();

            // ---- fw dense: 64 outs, K4=32, 4-way k-split (256 threads) ----
            if (tid < 256) {
                int n = tid & 63, kh = tid >> 6;
                part_a[tid] = dotp1<8>(g_wp + OFF_FW + kh * 8 * 64, n, 64,
                                       &fwin[kh * 32]);
            }
            __syncthreads();
            if (tid < 64) {
                int n = tid;
                tmp[n] = tanhf(part_a[n] + part_a[64 + n] +
                               part_a[128 + n] + part_a[192 + n]);
            }
            __syncthreads();

            // ---- fw GLU: 64 outs, K4=16, 4-way split ----
            if (tid < 256) {
                int n = tid & 63, kh = tid >> 6;
                part_a[tid] = dotp1<4>(g_wp + OFF_FWGLU + kh * 4 * 64, n, 64,
                                       &tmp[kh * 16]);
            }
            __syncthreads();
            if (tid < 64) {
                int n = tid;
                float d = part_a[n] + part_a[64 + n] + part_a[128 + n] + part_a[192 + n];
                sfr[192 + n] = clip1(tmp[n] * sigm(d) + nbuf[128 + n]);  // stream 2
            }
            __syncthreads();

            // ================= GRU blocks =================
#define GRU_GATES_1(WIHOFF, WHHOFF, H)                                         \
            {                                                                  \
                int n = tid % 192, kh = tid / 192;                             \
                part_a[tid] = dotp1<16>(g_wp + (WIHOFF) + kh * 16 * 192, n, 192, \
                                        &sfr[192 + kh * 64]);                  \
                part_b[tid] = dotp1<8>(g_wp + (WHHOFF) + kh * 8 * 192, n, 192, \
                                       &(H)[kh * 32]);                         \
            }
#define GRU_GATES_2(WIHOFF, WHHOFF, GOFF, H)                                   \
            {                                                                  \
                int n = tid % 192, kh = tid / 192;                             \
                const float* a0 = kh ? &sfr[256] : &sfr[GOFF];                 \
                part_a[tid] = dotp1<16>(g_wp + (WIHOFF) + kh * 16 * 192, n, 192, a0); \
                part_b[tid] = dotp1<8>(g_wp + (WHHOFF) + kh * 8 * 192, n, 192, \
                                       &(H)[kh * 32]);                         \
            }
#define GRU_COMBINE(H, KH)                                                     \
            if (tid < 64) {                                                    \
                int j = tid;                                                   \
                float gir = part_a[j]       + part_a[192 + j];                 \
                float giz = part_a[64 + j]  + part_a[256 + j];                 \
                float gin = part_a[128 + j] + part_a[320 + j];                 \
                float ghr = part_b[j]       + part_b[192 + j];                 \
                float ghz = part_b[64 + j]  + part_b[256 + j];                 \
                float ghn = part_b[128 + j] + part_b[320 + j];                 \
                float hv = (H)[j];                                             \
                float rr = sigm(gir + ghr);                                    \
                float zz = sigm(giz + ghz);                                    \
                float nn = tanhf(gin + rr * ghn);                              \
                float nh = (1.0f - zz) * nn + zz * hv;                         \
                (H)[j] = nh;                                                   \
                tmp[j] = clip1(nh + nbuf[(KH) * 64 + j]);                      \
            }
#define GLU_PHASE(GLUOFF, DSTOFF, KG)                                          \
            if (tid < 256) {                                                   \
                int n = tid & 63, kh = tid >> 6;                               \
                part_a[tid] = dotp1<4>(g_wp + (GLUOFF) + kh * 4 * 64, n, 64,   \
                                       &tmp[kh * 16]);                         \
            }                                                                  \
            __syncthreads();                                                   \
            if (tid < 64) {                                                    \
                int n = tid;                                                   \
                float d = part_a[n] + part_a[64 + n] + part_a[128 + n] + part_a[192 + n]; \
                sfr[(DSTOFF) + n] = clip1(tmp[n] * sigm(d) + nbuf[(KG) * 64 + n]); \
            }

            // GRU1 (input = concat(fw, prevn), contiguous at sfr+192)
            GRU_GATES_1(OFF_WIH1, OFF_WHH1, h1);
            __syncthreads();
            GRU_COMBINE(h1, 3);
            __syncthreads();
            GLU_PHASE(OFF_GLU1, 0, 4);
            __syncthreads();

            // GRU2 (input = concat(g1 @ sfr+0, prevn @ sfr+256))
            GRU_GATES_2(OFF_WIH2, OFF_WHH2, 0, h2);
            __syncthreads();
            GRU_COMBINE(h2, 5);
            __syncthreads();
            GLU_PHASE(OFF_GLU2, 64, 6);
            __syncthreads();

            // GRU3 (input = concat(g2 @ sfr+64, prevn @ sfr+256))
            GRU_GATES_2(OFF_WIH3, OFF_WHH3, 64, h3);
            __syncthreads();
            GRU_COMBINE(h3, 7);
            __syncthreads();
            GLU_PHASE(OFF_GLU3, 128, 8);
            __syncthreads();

            // ---- skip dense: 128 outs, K4=80, 27/27/26 (384 thr) ----
            {
                int n = tid & 127, seg = tid >> 7;
                if (seg == 0)
                    part_a[tid] = dotp1<27>(g_wp + OFF_SKIPD, n, 128, &sfr[0]);
                else if (seg == 1)
                    part_a[tid] = dotp1<27>(g_wp + OFF_SKIPD + 27 * 128, n, 128,
                                            &sfr[108]);
                else
                    part_a[tid] = dotp1<26>(g_wp + OFF_SKIPD + 54 * 128, n, 128,
                                            &sfr[216]);
            }
            __syncthreads();
            if (tid < 128) {
                int n = tid;
                float d = part_a[n] + part_a[128 + n] + part_a[256 + n];
                skb[n] = clip1(tanhf(d) + nbuf[576 + n]);      // stream 9
            }
            __syncthreads();

            // ---- skip GLU: 128 outs, K4=32, 2-way split (256 thr) ----
            if (tid < 256) {
                int n = tid & 127, kh = tid >> 7;
                part_a[tid] = dotp1<16>(g_wp + OFF_SKIPG + kh * 16 * 128, n, 128,
                                        &skb[kh * 64]);
            }
            __syncthreads();
            if (tid < 128) {
                int n = tid;
                float d = part_a[n] + part_a[128 + n];
                sk2[n] = skb[n] * sigm(d);
            }
            __syncthreads();

            // ---- out: 64 outs; idle warps stage next step's noise ----
            if (tid < 256) {
                int n = tid & 63, kh = tid >> 6;
                part_a[tid] = dotp1<8>(g_wp + OFF_OUT + kh * 8 * 64, n, 64,
                                       &sk2[kh * 32]);
            } else if (step < 399) {
                STAGE_NOISE(step + 1, tid - 256, 128);
            }
            __syncthreads();
            if (tid < 64) {
                int n = tid;
                float d = part_a[n] + part_a[64 + n] + part_a[128 + n] + part_a[192 + n];
                float ox = tanhf(d);
                out[b * 25600 + t * 256 + s * 64 + n] = ox;
                prev[n] = ox;
            }
            __syncthreads();
        }
    }
#undef STAGE_NOISE
}

// ------------------------------- launcher ----------------------------------
extern "C" void kernel_launch(void* const* d_in, const int* in_sizes, int n_in,
                              void* d_out, int out_size) {
    const float* features = (const float*)d_in[0];
    const float* gfeat    = (const float*)d_in[1];
    const float* in_W1    = (const float*)d_in[2];
    const float* in_b1    = (const float*)d_in[3];
    const float* in_W2    = (const float*)d_in[4];
    const float* in_b2    = (const float*)d_in[5];
    const float* fw_W     = (const float*)d_in[6];
    const float* fw_glu_W = (const float*)d_in[7];
    const float* g1_Wih   = (const float*)d_in[8];
    const float* g1_Whh   = (const float*)d_in[9];
    const float* glu1_W   = (const float*)d_in[10];
    const float* g2_Wih   = (const float*)d_in[11];
    const float* g2_Whh   = (const float*)d_in[12];
    const float* glu2_W   = (const float*)d_in[13];
    const float* g3_Wih   = (const float*)d_in[14];
    const float* g3_Whh   = (const float*)d_in[15];
    const float* glu3_W   = (const float*)d_in[16];
    const float* skipd_W  = (const float*)d_in[17];
    const float* skipg_W  = (const float*)d_in[18];
    const float* out_W    = (const float*)d_in[19];
    float* out = (float*)d_out;

    // noise precomputation (partitionable threefry)
    gen_keys<<<(4000 + 127) / 128, 128>>>();
    gen_noise<<<dim3(176, 400), 256>>>();

    // input MLP (all frames)
    build_a1<<<12800, 256>>>(features, gfeat);
    gemm1<<<dim3(100, 8), 256>>>(in_W1, in_b1);
    gemm2<<<dim3(100, 4), 256>>>(in_W2, in_b2);

    // pack recurrent weights
    auto P = [](const float* src, int off, int N, int K) {
        int cnt = N * (K / 4);
        packw<<<(cnt + 255) / 256, 256>>>(src, off, N, K / 4);
    };
    P(fw_W,    OFF_FW,    64, 128);
    P(fw_glu_W,OFF_FWGLU, 64, 64);
    P(g1_Wih,  OFF_WIH1, 192, 128);
    P(g1_Whh,  OFF_WHH1, 192, 64);
    P(glu1_W,  OFF_GLU1,  64, 64);
    P(g2_Wih,  OFF_WIH2, 192, 128);
    P(g2_Whh,  OFF_WHH2, 192, 64);
    P(glu2_W,  OFF_GLU2,  64, 64);
    P(g3_Wih,  OFF_WIH3, 192, 128);
    P(g3_Whh,  OFF_WHH3, 192, 64);
    P(glu3_W,  OFF_GLU3,  64, 64);
    P(skipd_W, OFF_SKIPD,128, 320);
    P(skipg_W, OFF_SKIPG,128, 128);
    P(out_W,   OFF_OUT,   64, 128);

    // sequential recurrent pass — one batch row per CTA
    fargan_rnn<<<64, 384>>>(out);
}

// round 17
// speedup vs baseline: 1.0596x; 1.0596x over previous
#include <cuda_runtime.h>
#include <stdint.h>
#include <stddef.h>

// ===========================================================================
// FARGAN vocoder. B=64, T=100, NSUB=4, S=64, HOP=256, IC=512.
// Stage 0: precompute ALL noise (partitionable threefry) -> g_nz
// Stage 1: input MLP for all frames (no recurrence)      -> g_X
// Stage 2: pack/transpose recurrent weights              -> g_wp
// Stage 3: sequential recurrent kernel, 64 CTAs x 768 thr, ONE row per CTA.
//          R10 structure; only change: 768 threads with finer k-splits to
//          shorten per-thread load chains and amortize phase-tail latency.
// ===========================================================================

__device__ float g_A1[6400 * 512];
__device__ float g_H [6400 * 512];
__device__ float g_X [6400 * 256];
__device__ float4 g_wp[50176];       // packed transposed recurrent weights
__device__ uint2 g_kk[4000];
__device__ float g_nz[18022400];     // 400 steps * 45056 noise values

// packed-weight offsets in g_wp (float4 units)
#define OFF_FW     0
#define OFF_FWGLU  2048
#define OFF_WIH1   3072
#define OFF_WHH1   9216
#define OFF_GLU1   12288
#define OFF_WIH2   13312
#define OFF_WHH2   19456
#define OFF_GLU2   22528
#define OFF_WIH3   23552
#define OFF_WHH3   29696
#define OFF_GLU3   32768
#define OFF_SKIPD  33792
#define OFF_SKIPG  44032
#define OFF_OUT    48128

// ----------------------------- threefry2x32 --------------------------------
__device__ __forceinline__ uint32_t rotl32(uint32_t v, int s) {
    return (v << s) | (v >> (32 - s));
}
__device__ __forceinline__ uint2 tf2x32(uint2 key, uint2 ctr) {
    uint32_t ks0 = key.x, ks1 = key.y;
    uint32_t ks2 = ks0 ^ ks1 ^ 0x1BD11BDAu;
    uint32_t x0 = ctr.x + ks0, x1 = ctr.y + ks1;
#define TFR(r) { x0 += x1; x1 = rotl32(x1, (r)); x1 ^= x0; }
    TFR(13) TFR(15) TFR(26) TFR(6)   x0 += ks1; x1 += ks2 + 1u;
    TFR(17) TFR(29) TFR(16) TFR(24)  x0 += ks2; x1 += ks0 + 2u;
    TFR(13) TFR(15) TFR(26) TFR(6)   x0 += ks0; x1 += ks1 + 3u;
    TFR(17) TFR(29) TFR(16) TFR(24)  x0 += ks1; x1 += ks2 + 4u;
    TFR(13) TFR(15) TFR(26) TFR(6)   x0 += ks2; x1 += ks0 + 5u;
#undef TFR
    return make_uint2(x0, x1);
}
__device__ __forceinline__ float nzf(uint32_t r) {
    float u = __uint_as_float((r >> 9) | 0x3f800000u) - 1.0f;
    return (u - 0.5f) * (1.0f / 127.0f);
}
__device__ __forceinline__ float clip1(float v) { return fminf(fmaxf(v, -1.0f), 1.0f); }
__device__ __forceinline__ float sigm(float x) { return 1.0f / (1.0f + expf(-x)); }

// ------------------------- noise precomputation ----------------------------
__global__ void gen_keys() {
    int idx = blockIdx.x * 128 + threadIdx.x;
    if (idx >= 4000) return;
    int step = idx / 10, q = idx % 10;
    uint2 fkey = tf2x32(make_uint2(0u, 1u), make_uint2(0u, (uint32_t)step));
    g_kk[idx] = tf2x32(fkey, make_uint2(0u, (uint32_t)q));
}
__global__ void gen_noise() {
    int rem = blockIdx.x * 256 + threadIdx.x;   // [0, 45056)
    int step = blockIdx.y;
    int q, f;
    if (rem < 36864) { q = rem >> 12; f = rem & 4095; }
    else             { q = 9;         f = rem - 36864; }
    uint2 kk = g_kk[step * 10 + q];
    uint2 c = tf2x32(kk, make_uint2(0u, (uint32_t)f));
    g_nz[(size_t)step * 45056 + rem] = nzf(c.x ^ c.y);
}

// ----------------------------- input MLP -----------------------------------
__global__ void build_a1(const float* __restrict__ feats, const float* __restrict__ gf) {
    int idx = blockIdx.x * blockDim.x + threadIdx.x;
    if (idx >= 6400 * 512) return;
    int row = idx >> 9;
    int k = idx & 511;
    int t = row >> 6, b = row & 63;
    float v;
    if (k < 256) v = feats[(b * 256 + k) * 100 + t];
    else         v = gf[b * 256 + (k - 256)];
    g_A1[idx] = v;
}

template <int ACT>
__device__ __forceinline__ void gemm_body(const float* __restrict__ A,
                                          const float* __restrict__ W,
                                          const float* __restrict__ bias,
                                          float* __restrict__ out, int N, int K) {
    __shared__ float As[64][17];
    __shared__ float Bs[16][65];
    const int bm = blockIdx.x * 64, bn = blockIdx.y * 64;
    const int tx = threadIdx.x & 15, ty = threadIdx.x >> 4;
    float acc[4][4] = {};
    for (int k0 = 0; k0 < K; k0 += 16) {
#pragma unroll
        for (int i = 0; i < 4; i++) {
            int lin = threadIdx.x + i * 256;
            int r = lin >> 4, c = lin & 15;
            As[r][c] = A[(bm + r) * K + k0 + c];
            Bs[c][r] = W[(bn + r) * K + k0 + c];
        }
        __syncthreads();
#pragma unroll
        for (int kk = 0; kk < 16; kk++) {
            float a[4], bb[4];
#pragma unroll
            for (int i = 0; i < 4; i++) a[i] = As[ty * 4 + i][kk];
#pragma unroll
            for (int j = 0; j < 4; j++) bb[j] = Bs[kk][tx * 4 + j];
#pragma unroll
            for (int i = 0; i < 4; i++)
#pragma unroll
                for (int j = 0; j < 4; j++)
                    acc[i][j] = fmaf(a[i], bb[j], acc[i][j]);
        }
        __syncthreads();
    }
#pragma unroll
    for (int i = 0; i < 4; i++) {
        int m = bm + ty * 4 + i;
#pragma unroll
        for (int j = 0; j < 4; j++) {
            int nn = bn + tx * 4 + j;
            float v = acc[i][j] + bias[nn];
            if (ACT) v = tanhf(v);
            out[m * N + nn] = v;
        }
    }
}
__global__ __launch_bounds__(256) void gemm1(const float* __restrict__ W,
                                             const float* __restrict__ b) {
    gemm_body<1>(g_A1, W, b, g_H, 512, 512);
}
__global__ __launch_bounds__(256) void gemm2(const float* __restrict__ W,
                                             const float* __restrict__ b) {
    gemm_body<0>(g_H, W, b, g_X, 256, 512);
}

// ----------------------- weight transpose/pack -----------------------------
__global__ void packw(const float* __restrict__ src, int off, int N, int K4) {
    int idx = blockIdx.x * blockDim.x + threadIdx.x;
    if (idx >= N * K4) return;
    int n = idx % N, kq = idx / N;
    const float* s = src + n * (K4 * 4) + 4 * kq;
    g_wp[off + idx] = make_float4(s[0], s[1], s[2], s[3]);
}

// ----------------------------- single-row dot ------------------------------
template <int LEN>
__device__ __forceinline__ float dotp1(const float4* __restrict__ wp, int n, int N,
                                       const float* __restrict__ x) {
    const float4* xa = reinterpret_cast<const float4*>(x);
    float a0 = 0.f, a1 = 0.f;
#pragma unroll
    for (int i = 0; i < LEN; i++) {
        float4 w = wp[i * N + n];
        float4 p = xa[i];
        a0 = fmaf(w.x, p.x, a0); a1 = fmaf(w.y, p.y, a1);
        a0 = fmaf(w.z, p.z, a0); a1 = fmaf(w.w, p.w, a1);
    }
    return a0 + a1;
}

// --------------------------- recurrent kernel ------------------------------
__global__ __launch_bounds__(768, 1) void fargan_rnn(float* __restrict__ out) {
    const int tid = threadIdx.x;
    const int b = blockIdx.x;             // ONE batch row per CTA

    __shared__ __align__(16) float sfr[320];    // [g1|g2|g3|fw|prevn]
    __shared__ __align__(16) float fwin[128];   // [sub_noised | s3]
    __shared__ __align__(16) float tmp[64];
    __shared__ __align__(16) float h1[64], h2[64], h3[64];
    __shared__ __align__(16) float prev[64];
    __shared__ __align__(16) float skb[128], sk2[128];
    __shared__ __align__(16) float part_a[768], part_b[768];
    __shared__ __align__(16) float nbuf[704];   // streams 0-8 @ q*64, 9 @ 576

    if (tid < 64) {
        h1[tid] = h2[tid] = h3[tid] = 0.f;
        prev[tid] = 0.f;
    }
    if (tid < 128) fwin[tid] = 0.f;
    __syncthreads();

#pragma unroll 1
    for (int t = 0; t < 100; t++) {
#pragma unroll 1
        for (int s = 0; s < 4; s++) {
            const int step = t * 4 + s;

            // ---- stage this step's noise for row b (176 float4 loads) ----
            if (tid < 176) {
                const float* nsrc = g_nz + (size_t)step * 45056;
                int goff, soff;
                if (tid < 144) {                    // streams 0..8 (64 each)
                    int q = tid >> 4, l = tid & 15;
                    goff = q * 4096 + b * 64 + l * 4;
                    soff = q * 64 + l * 4;
                } else {                            // stream 9 (128)
                    int l = tid - 144;
                    goff = 36864 + b * 128 + l * 4;
                    soff = 576 + l * 4;
                }
                *reinterpret_cast<float4*>(nbuf + soff) =
                    *reinterpret_cast<const float4*>(nsrc + goff);
            }
            __syncthreads();

            // ---- phase A: noise sub + prev, shift s3 (64 threads) ----
            if (tid < 64) {
                int j = tid;
                float sx = g_X[(t * 64 + b) * 256 + s * 64 + j];
                float olds = fwin[j];
                fwin[64 + j] = olds;                          // s3
                fwin[j] = clip1(sx + nbuf[j]);                // stream 0
                sfr[256 + j] = clip1(prev[j] + nbuf[64 + j]); // stream 1
            }
            __syncthreads();

            // ---- fw dense: 64 outs, K4=32, 8-way k-split (512 threads) ----
            if (tid < 512) {
                int n = tid & 63, kh = tid >> 6;
                part_a[tid] = dotp1<4>(g_wp + OFF_FW + kh * 4 * 64, n, 64,
                                       &fwin[kh * 16]);
            }
            __syncthreads();
            if (tid < 64) {
                int n = tid;
                float d = 0.f;
#pragma unroll
                for (int k = 0; k < 8; k++) d += part_a[k * 64 + n];
                tmp[n] = tanhf(d);
            }
            __syncthreads();

            // ---- fw GLU: 64 outs, K4=16, 8-way split (512 threads) ----
            if (tid < 512) {
                int n = tid & 63, kh = tid >> 6;
                part_a[tid] = dotp1<2>(g_wp + OFF_FWGLU + kh * 2 * 64, n, 64,
                                       &tmp[kh * 8]);
            }
            __syncthreads();
            if (tid < 64) {
                int n = tid;
                float d = 0.f;
#pragma unroll
                for (int k = 0; k < 8; k++) d += part_a[k * 64 + n];
                sfr[192 + n] = clip1(tmp[n] * sigm(d) + nbuf[128 + n]);  // stream 2
            }
            __syncthreads();

            // ================= GRU blocks =================
            // gates: 768 threads, n = tid%192, kh = tid/192 (4-way k-split)
#define GRU_GATES_1(WIHOFF, WHHOFF, H)                                         \
            {                                                                  \
                int n = tid % 192, kh = tid / 192;                             \
                part_a[tid] = dotp1<8>(g_wp + (WIHOFF) + kh * 8 * 192, n, 192, \
                                       &sfr[192 + kh * 32]);                   \
                part_b[tid] = dotp1<4>(g_wp + (WHHOFF) + kh * 4 * 192, n, 192, \
                                       &(H)[kh * 16]);                         \
            }
#define GRU_GATES_2(WIHOFF, WHHOFF, GOFF, H)                                   \
            {                                                                  \
                int n = tid % 192, kh = tid / 192;                             \
                const float* a0 = (kh & 2) ? &sfr[256 + (kh & 1) * 32]         \
                                           : &sfr[(GOFF) + (kh & 1) * 32];     \
                part_a[tid] = dotp1<8>(g_wp + (WIHOFF) + kh * 8 * 192, n, 192, a0); \
                part_b[tid] = dotp1<4>(g_wp + (WHHOFF) + kh * 4 * 192, n, 192, \
                                       &(H)[kh * 16]);                         \
            }
            // combine: 64 threads, 4-term sums
#define GRU_COMBINE(H, KH)                                                     \
            if (tid < 64) {                                                    \
                int j = tid;                                                   \
                float gir = 0.f, giz = 0.f, gin = 0.f;                         \
                float ghr = 0.f, ghz = 0.f, ghn = 0.f;                         \
                _Pragma("unroll")                                              \
                for (int k = 0; k < 4; k++) {                                  \
                    gir += part_a[k * 192 + j];                                \
                    giz += part_a[k * 192 + 64 + j];                           \
                    gin += part_a[k * 192 + 128 + j];                          \
                    ghr += part_b[k * 192 + j];                                \
                    ghz += part_b[k * 192 + 64 + j];                           \
                    ghn += part_b[k * 192 + 128 + j];                          \
                }                                                              \
                float hv = (H)[j];                                             \
                float rr = sigm(gir + ghr);                                    \
                float zz = sigm(giz + ghz);                                    \
                float nn = tanhf(gin + rr * ghn);                              \
                float nh = (1.0f - zz) * nn + zz * hv;                         \
                (H)[j] = nh;                                                   \
                tmp[j] = clip1(nh + nbuf[(KH) * 64 + j]);                      \
            }
            // GLU: 64 outs, K4=16, 8-way split (512 threads)
#define GLU_PHASE(GLUOFF, DSTOFF, KG)                                          \
            if (tid < 512) {                                                   \
                int n = tid & 63, kh = tid >> 6;                               \
                part_a[tid] = dotp1<2>(g_wp + (GLUOFF) + kh * 2 * 64, n, 64,   \
                                       &tmp[kh * 8]);                          \
            }                                                                  \
            __syncthreads();                                                   \
            if (tid < 64) {                                                    \
                int n = tid;                                                   \
                float d = 0.f;                                                 \
                _Pragma("unroll")                                              \
                for (int k = 0; k < 8; k++) d += part_a[k * 64 + n];           \
                sfr[(DSTOFF) + n] = clip1(tmp[n] * sigm(d) + nbuf[(KG) * 64 + n]); \
            }

            // GRU1 (input = concat(fw, prevn), contiguous at sfr+192)
            GRU_GATES_1(OFF_WIH1, OFF_WHH1, h1);
            __syncthreads();
            GRU_COMBINE(h1, 3);
            __syncthreads();
            GLU_PHASE(OFF_GLU1, 0, 4);
            __syncthreads();

            // GRU2 (input = concat(g1 @ sfr+0, prevn @ sfr+256))
            GRU_GATES_2(OFF_WIH2, OFF_WHH2, 0, h2);
            __syncthreads();
            GRU_COMBINE(h2, 5);
            __syncthreads();
            GLU_PHASE(OFF_GLU2, 64, 6);
            __syncthreads();

            // GRU3 (input = concat(g2 @ sfr+64, prevn @ sfr+256))
            GRU_GATES_2(OFF_WIH3, OFF_WHH3, 64, h3);
            __syncthreads();
            GRU_COMBINE(h3, 7);
            __syncthreads();
            GLU_PHASE(OFF_GLU3, 128, 8);
            __syncthreads();

            // ---- skip dense: 128 outs, K4=80, 6-way 14x5+10 (768 thr) ----
            {
                int n = tid & 127, seg = tid >> 7;   // 0..5
                if (seg < 5)
                    part_a[tid] = dotp1<14>(g_wp + OFF_SKIPD + seg * 14 * 128,
                                            n, 128, &sfr[seg * 56]);
                else
                    part_a[tid] = dotp1<10>(g_wp + OFF_SKIPD + 70 * 128,
                                            n, 128, &sfr[280]);
            }
            __syncthreads();
            if (tid < 128) {
                int n = tid;
                float d = 0.f;
#pragma unroll
                for (int k = 0; k < 6; k++) d += part_a[k * 128 + n];
                skb[n] = clip1(tanhf(d) + nbuf[576 + n]);      // stream 9
            }
            __syncthreads();

            // ---- skip GLU: 128 outs, K4=32, 4-way split (512 thr) ----
            if (tid < 512) {
                int n = tid & 127, kh = tid >> 7;
                part_a[tid] = dotp1<8>(g_wp + OFF_SKIPG + kh * 8 * 128, n, 128,
                                       &skb[kh * 32]);
            }
            __syncthreads();
            if (tid < 128) {
                int n = tid;
                float d = part_a[n] + part_a[128 + n] + part_a[256 + n] + part_a[384 + n];
                sk2[n] = skb[n] * sigm(d);
            }
            __syncthreads();

            // ---- out: 64 outs, K4=32, 8-way split (512 thr) ----
            if (tid < 512) {
                int n = tid & 63, kh = tid >> 6;
                part_a[tid] = dotp1<4>(g_wp + OFF_OUT + kh * 4 * 64, n, 64,
                                       &sk2[kh * 16]);
            }
            __syncthreads();
            if (tid < 64) {
                int n = tid;
                float d = 0.f;
#pragma unroll
                for (int k = 0; k < 8; k++) d += part_a[k * 64 + n];
                float ox = tanhf(d);
                out[b * 25600 + t * 256 + s * 64 + n] = ox;
                prev[n] = ox;
            }
            __syncthreads();
        }
    }
}

// ------------------------------- launcher ----------------------------------
extern "C" void kernel_launch(void* const* d_in, const int* in_sizes, int n_in,
                              void* d_out, int out_size) {
    const float* features = (const float*)d_in[0];
    const float* gfeat    = (const float*)d_in[1];
    const float* in_W1    = (const float*)d_in[2];
    const float* in_b1    = (const float*)d_in[3];
    const float* in_W2    = (const float*)d_in[4];
    const float* in_b2    = (const float*)d_in[5];
    const float* fw_W     = (const float*)d_in[6];
    const float* fw_glu_W = (const float*)d_in[7];
    const float* g1_Wih   = (const float*)d_in[8];
    const float* g1_Whh   = (const float*)d_in[9];
    const float* glu1_W   = (const float*)d_in[10];
    const float* g2_Wih   = (const float*)d_in[11];
    const float* g2_Whh   = (const float*)d_in[12];
    const float* glu2_W   = (const float*)d_in[13];
    const float* g3_Wih   = (const float*)d_in[14];
    const float* g3_Whh   = (const float*)d_in[15];
    const float* glu3_W   = (const float*)d_in[16];
    const float* skipd_W  = (const float*)d_in[17];
    const float* skipg_W  = (const float*)d_in[18];
    const float* out_W    = (const float*)d_in[19];
    float* out = (float*)d_out;

    // noise precomputation (partitionable threefry)
    gen_keys<<<(4000 + 127) / 128, 128>>>();
    gen_noise<<<dim3(176, 400), 256>>>();

    // input MLP (all frames)
    build_a1<<<12800, 256>>>(features, gfeat);
    gemm1<<<dim3(100, 8), 256>>>(in_W1, in_b1);
    gemm2<<<dim3(100, 4), 256>>>(in_W2, in_b2);

    // pack recurrent weights
    auto P = [](const float* src, int off, int N, int K) {
        int cnt = N * (K / 4);
        packw<<<(cnt + 255) / 256, 256>>>(src, off, N, K / 4);
    };
    P(fw_W,    OFF_FW,    64, 128);
    P(fw_glu_W,OFF_FWGLU, 64, 64);
    P(g1_Wih,  OFF_WIH1, 192, 128);
    P(g1_Whh,  OFF_WHH1, 192, 64);
    P(glu1_W,  OFF_GLU1,  64, 64);
    P(g2_Wih,  OFF_WIH2, 192, 128);
    P(g2_Whh,  OFF_WHH2, 192, 64);
    P(glu2_W,  OFF_GLU2,  64, 64);
    P(g3_Wih,  OFF_WIH3, 192, 128);
    P(g3_Whh,  OFF_WHH3, 192, 64);
    P(glu3_W,  OFF_GLU3,  64, 64);
    P(skipd_W, OFF_SKIPD,128, 320);
    P(skipg_W, OFF_SKIPG,128, 128);
    P(out_W,   OFF_OUT,   64, 128);

    // sequential recurrent pass — one batch row per CTA, 768 threads
    fargan_rnn<<<64, 768>>>(out);
}